// round 4
// baseline (speedup 1.0000x reference)
#include <cuda_runtime.h>

#define NA      8000
#define MP      1200000
#define NCDIM   8
#define NCELL   512
#define ROWCAP  192
#define RPB     8      /* rows (warps) per block in k_rows / k_emit */

// ---------------- device scratch (no allocations allowed) ----------------
__device__ float4 g_pos4[NA];        // original order: x,y,z,|p|^2
__device__ float4 g_pos4s[NA];       // cell-sorted copy
__device__ int    g_orig[NA];        // sorted slot -> original atom index
__device__ int    g_cellid[NA];
__device__ int    g_ccount[NCELL];   // zero at start of every call (self-restoring)
__device__ int    g_cstart[NCELL + 1];
__device__ int    g_rcount[NA];
__device__ int    g_roff[NA];
__device__ int    g_total;
__device__ int    g_done;            // zero at start of every call (self-restoring)
__device__ int    g_scratch[NA * ROWCAP];

__device__ __forceinline__ int cellco(float x) {
    int c = (int)(x * 0.2f);
    return min(7, max(0, c));
}

// ---------------- kernels ----------------
__global__ void k_prep(const float* __restrict__ pos) {
    int i = blockIdx.x * blockDim.x + threadIdx.x;
    if (i >= NA) return;
    float x = pos[3 * i + 0];
    float y = pos[3 * i + 1];
    float z = pos[3 * i + 2];
    // sq = (x*x + y*y) + z*z, strict fp32, NO FMA (XLA mul+reduce fusion)
    float sq = __fadd_rn(__fadd_rn(__fmul_rn(x, x), __fmul_rn(y, y)), __fmul_rn(z, z));
    g_pos4[i] = make_float4(x, y, z, sq);
    int c = (cellco(z) * NCDIM + cellco(y)) * NCDIM + cellco(x);
    g_cellid[i] = c;
    atomicAdd(&g_ccount[c], 1);
}

// fused cell-offset scan + counter reset + scatter (one block, smem cursors)
__global__ void __launch_bounds__(1024) k_build() {
    __shared__ int sh[NCELL];
    __shared__ int cur[NCELL];
    int t = threadIdx.x;
    int v0 = 0;
    if (t < NCELL) { v0 = g_ccount[t]; sh[t] = v0; }
    __syncthreads();
    for (int d = 1; d < NCELL; d <<= 1) {
        int v = 0;
        if (t < NCELL && t >= d) v = sh[t - d];
        __syncthreads();
        if (t < NCELL) sh[t] += v;
        __syncthreads();
    }
    if (t < NCELL) {
        int incl = sh[t];
        int excl = incl - v0;
        g_cstart[t] = excl;
        cur[t] = excl;
        g_ccount[t] = 0;                 // restore invariant for next call
        if (t == NCELL - 1) g_cstart[NCELL] = incl;
    }
    __syncthreads();
    for (int i = t; i < NA; i += 1024) {
        int c = g_cellid[i];
        int p = atomicAdd(&cur[c], 1);
        g_orig[p] = i;
        g_pos4s[p] = g_pos4[i];
    }
}

__global__ void __launch_bounds__(RPB * 32) k_rows() {
    __shared__ unsigned mask[RPB][256];
    int warp = threadIdx.x >> 5;
    int lane = threadIdx.x & 31;
    int i = blockIdx.x * RPB + warp;
    unsigned* m = mask[warp];
    #pragma unroll
    for (int w = lane; w < 256; w += 32) m[w] = 0u;
    __syncwarp();

    float4 pi = g_pos4[i];
    int cx = cellco(pi.x), cy = cellco(pi.y), cz = cellco(pi.z);
    // dist < 5  <=>  RN(sqrt(d2)) < 5  <=>  d2 < nextbelow(25.0f)
    const float T = __int_as_float(0x41C7FFFF);
    int zlo = max(cz - 1, 0), zhi = min(cz + 1, 7);
    int ylo = max(cy - 1, 0), yhi = min(cy + 1, 7);
    int xlo = max(cx - 1, 0), xhi = min(cx + 1, 7);
    for (int zz = zlo; zz <= zhi; zz++)
        for (int yy = ylo; yy <= yhi; yy++) {
            int crow = (zz * NCDIM + yy) * NCDIM;
            int s = g_cstart[crow + xlo];
            int e = g_cstart[crow + xhi + 1];   // x-adjacent cells are contiguous
            for (int k = s + lane; k < e; k += 32) {
                float4 pj = g_pos4s[k];
                // Eigen-style FMA chain: dot = fma(z, fma(y, rn(x*x')))
                float dt = __fmaf_rn(pi.z, pj.z,
                            __fmaf_rn(pi.y, pj.y,
                             __fmul_rn(pi.x, pj.x)));
                float d2 = __fsub_rn(__fadd_rn(pi.w, pj.w), __fmul_rn(2.0f, dt));
                int j = g_orig[k];
                if (d2 < T && j != i)
                    atomicOr(&m[j >> 5], 1u << (j & 31));
            }
        }
    __syncwarp();

    // lane-parallel ordered (ascending-j) emission: lane owns words [8l, 8l+8)
    {
        unsigned words[8];
        int cnt = 0;
        uint4 wa = ((const uint4*)m)[lane * 2 + 0];
        uint4 wb = ((const uint4*)m)[lane * 2 + 1];
        words[0] = wa.x; words[1] = wa.y; words[2] = wa.z; words[3] = wa.w;
        words[4] = wb.x; words[5] = wb.y; words[6] = wb.z; words[7] = wb.w;
        #pragma unroll
        for (int u = 0; u < 8; u++) cnt += __popc(words[u]);
        int x = cnt;
        #pragma unroll
        for (int d = 1; d < 32; d <<= 1) {
            int y = __shfl_up_sync(0xFFFFFFFFu, x, d);
            if (lane >= d) x += y;
        }
        int r = x - cnt;                                   // exclusive prefix
        int total = __shfl_sync(0xFFFFFFFFu, x, 31);
        int base = i * ROWCAP;
        #pragma unroll
        for (int u = 0; u < 8; u++) {
            unsigned mm = words[u];
            int jbase = (lane * 8 + u) * 32;
            while (mm) {
                int b = __ffs(mm) - 1;
                mm &= mm - 1;
                if (r < ROWCAP) g_scratch[base + r] = jbase + b;
                r++;
            }
        }
        if (lane == 0) g_rcount[i] = min(total, ROWCAP);
    }

    // ---- last-finishing block performs the row-offset scan ----
    __shared__ int s_ticket;
    __threadfence();
    __syncthreads();
    if (threadIdx.x == 0) s_ticket = atomicAdd(&g_done, 1);
    __syncthreads();
    if (s_ticket != (int)gridDim.x - 1) return;
    if (threadIdx.x == 0) g_done = 0;   // restore invariant
    __threadfence();

    {
        const int PER = 32;  // 256 * 32 = 8192 >= NA
        __shared__ int wsum[8];
        int t = threadIdx.x;
        int v[PER];
        int s = 0;
        #pragma unroll
        for (int u = 0; u < PER; u++) {
            int idx = t * PER + u;
            v[u] = (idx < NA) ? g_rcount[idx] : 0;
            s += v[u];
        }
        int ln = t & 31, wd = t >> 5;
        int x = s;
        #pragma unroll
        for (int d = 1; d < 32; d <<= 1) {
            int y = __shfl_up_sync(0xFFFFFFFFu, x, d);
            if (ln >= d) x += y;
        }
        if (ln == 31) wsum[wd] = x;
        __syncthreads();
        if (t == 0) {
            int acc = 0;
            #pragma unroll
            for (int w = 0; w < 8; w++) { int tmp = wsum[w]; wsum[w] = acc; acc += tmp; }
            g_total = acc;
        }
        __syncthreads();
        int excl = wsum[wd] + (x - s);
        #pragma unroll
        for (int u = 0; u < PER; u++) {
            int idx = t * PER + u;
            if (idx < NA) g_roff[idx] = excl;
            excl += v[u];
        }
    }
}

__global__ void __launch_bounds__(RPB * 32) k_emit(float* __restrict__ out) {
    int warp = threadIdx.x >> 5;
    int lane = threadIdx.x & 31;
    int i = blockIdx.x * RPB + warp;
    {
        int c = g_rcount[i];
        int o = g_roff[i];
        float4 pi = g_pos4[i];
        float fi = (float)i;
        for (int k = lane; k < c; k += 32) {
            int idx = o + k;
            if (idx < MP) {
                int j = g_scratch[i * ROWCAP + k];
                float4 pj = g_pos4[j];
                float dx = pj.x - pi.x;
                float dy = pj.y - pi.y;
                float dz = pj.z - pi.z;
                float ds = sqrtf(dx * dx + dy * dy + dz * dz);
                ((float2*)out)[idx] = make_float2(fi, (float)j);
                out[2 * MP + idx] = (i < j) ? 1.0f : 0.0f;
                out[3 * MP + idx] = ds;
            }
        }
    }
    // zero-fill only the padding tail [total, MP) of each section
    int total = g_total;
    int tid = blockIdx.x * blockDim.x + threadIdx.x;
    int stride = gridDim.x * blockDim.x;
    for (int idx = total + tid; idx < MP; idx += stride) {
        ((float2*)out)[idx] = make_float2(0.f, 0.f);
        out[2 * MP + idx] = 0.f;
        out[3 * MP + idx] = 0.f;
    }
}

// ---------------- launch ----------------
extern "C" void kernel_launch(void* const* d_in, const int* in_sizes, int n_in,
                              void* d_out, int out_size) {
    const float* pos = (const float*)d_in[0];
    float* out = (float*)d_out;

    k_prep<<<(NA + 255) / 256, 256>>>(pos);
    k_build<<<1, 1024>>>();
    k_rows<<<NA / RPB, RPB * 32>>>();
    k_emit<<<NA / RPB, RPB * 32>>>(out);
}

// round 6
// speedup vs baseline: 1.1715x; 1.1715x over previous
#include <cuda_runtime.h>

#define NA      8000
#define MP      1200000
#define NCDIM   8
#define NCELL   512
#define ROWCAP  192
#define RPB     16     /* rows (warps) per block in k_rows / k_emit */

// ---------------- device scratch (no allocations allowed) ----------------
__device__ float4 g_pos4[NA];        // original order: x,y,z,|p|^2
__device__ float4 g_pos4s[NA];       // cell-sorted: x,y,z,bitcast(orig index)
__device__ int    g_cellid[NA];
__device__ int    g_ccount[NCELL];   // zero at start of every call (self-restoring)
__device__ int    g_cstart[NCELL + 1];
__device__ int    g_rcount[NA];
__device__ int    g_roff[NA];
__device__ int    g_total;
__device__ int    g_scratch[NA * ROWCAP];

__device__ __forceinline__ int cellco(float x) {
    int c = (int)(x * 0.2f);
    return min(7, max(0, c));
}

// ---------------- kernels ----------------
__global__ void k_prep(const float* __restrict__ pos) {
    int i = blockIdx.x * blockDim.x + threadIdx.x;
    if (i >= NA) return;
    float x = pos[3 * i + 0];
    float y = pos[3 * i + 1];
    float z = pos[3 * i + 2];
    // sq = (x*x + y*y) + z*z, strict fp32, NO FMA (XLA mul+reduce fusion)
    float sq = __fadd_rn(__fadd_rn(__fmul_rn(x, x), __fmul_rn(y, y)), __fmul_rn(z, z));
    g_pos4[i] = make_float4(x, y, z, sq);
    int c = (cellco(z) * NCDIM + cellco(y)) * NCDIM + cellco(x);
    g_cellid[i] = c;
    atomicAdd(&g_ccount[c], 1);
}

// fused cell-offset scan + counter reset + scatter (one block, smem cursors)
__global__ void __launch_bounds__(1024) k_build() {
    __shared__ int sh[NCELL];
    __shared__ int cur[NCELL];
    int t = threadIdx.x;
    int v0 = 0;
    if (t < NCELL) { v0 = g_ccount[t]; sh[t] = v0; }
    __syncthreads();
    for (int d = 1; d < NCELL; d <<= 1) {
        int v = 0;
        if (t < NCELL && t >= d) v = sh[t - d];
        __syncthreads();
        if (t < NCELL) sh[t] += v;
        __syncthreads();
    }
    if (t < NCELL) {
        int incl = sh[t];
        int excl = incl - v0;
        g_cstart[t] = excl;
        cur[t] = excl;
        g_ccount[t] = 0;                 // restore invariant for next call
        if (t == NCELL - 1) g_cstart[NCELL] = incl;
    }
    __syncthreads();
    for (int i = t; i < NA; i += 1024) {
        int c = g_cellid[i];
        int p = atomicAdd(&cur[c], 1);
        float4 q = g_pos4[i];
        g_pos4s[p] = make_float4(q.x, q.y, q.z, __int_as_float(i));
    }
}

__global__ void __launch_bounds__(RPB * 32) k_rows() {
    __shared__ unsigned mask[RPB][256];
    int warp = threadIdx.x >> 5;
    int lane = threadIdx.x & 31;
    int i = blockIdx.x * RPB + warp;
    unsigned* m = mask[warp];
    #pragma unroll
    for (int w = lane; w < 256; w += 32) m[w] = 0u;
    __syncwarp();

    float4 pi = g_pos4[i];
    int cx = cellco(pi.x), cy = cellco(pi.y), cz = cellco(pi.z);
    // dist < 5  <=>  RN(sqrt(d2)) < 5  <=>  d2 < nextbelow(25.0f)
    const float T = __int_as_float(0x41C7FFFF);
    int zlo = max(cz - 1, 0), zhi = min(cz + 1, 7);
    int ylo = max(cy - 1, 0), yhi = min(cy + 1, 7);
    int xlo = max(cx - 1, 0), xhi = min(cx + 1, 7);
    for (int zz = zlo; zz <= zhi; zz++)
        for (int yy = ylo; yy <= yhi; yy++) {
            int crow = (zz * NCDIM + yy) * NCDIM;
            int s = g_cstart[crow + xlo];
            int e = g_cstart[crow + xhi + 1];   // x-adjacent cells are contiguous
            for (int k = s + lane; k < e; k += 32) {
                float4 pj = g_pos4s[k];
                // sq_j recomputed with the exact k_prep sequence (bit-identical)
                float sqj = __fadd_rn(__fadd_rn(__fmul_rn(pj.x, pj.x),
                                                __fmul_rn(pj.y, pj.y)),
                                      __fmul_rn(pj.z, pj.z));
                // Eigen-style FMA chain: dot = fma(z, fma(y, rn(x*x')))
                float dt = __fmaf_rn(pi.z, pj.z,
                            __fmaf_rn(pi.y, pj.y,
                             __fmul_rn(pi.x, pj.x)));
                float d2 = __fsub_rn(__fadd_rn(pi.w, sqj), __fmul_rn(2.0f, dt));
                int j = __float_as_int(pj.w);
                if (d2 < T && j != i)
                    atomicOr(&m[j >> 5], 1u << (j & 31));
            }
        }
    __syncwarp();

    // lane-parallel ordered (ascending-j) emission: lane owns words [8l, 8l+8)
    unsigned words[8];
    int cnt = 0;
    uint4 wa = ((const uint4*)m)[lane * 2 + 0];
    uint4 wb = ((const uint4*)m)[lane * 2 + 1];
    words[0] = wa.x; words[1] = wa.y; words[2] = wa.z; words[3] = wa.w;
    words[4] = wb.x; words[5] = wb.y; words[6] = wb.z; words[7] = wb.w;
    #pragma unroll
    for (int u = 0; u < 8; u++) cnt += __popc(words[u]);
    int x = cnt;
    #pragma unroll
    for (int d = 1; d < 32; d <<= 1) {
        int y = __shfl_up_sync(0xFFFFFFFFu, x, d);
        if (lane >= d) x += y;
    }
    int r = x - cnt;                                   // exclusive prefix
    int total = __shfl_sync(0xFFFFFFFFu, x, 31);
    int base = i * ROWCAP;
    #pragma unroll
    for (int u = 0; u < 8; u++) {
        unsigned mm = words[u];
        int jbase = (lane * 8 + u) * 32;
        while (mm) {
            int b = __ffs(mm) - 1;
            mm &= mm - 1;
            if (r < ROWCAP) g_scratch[base + r] = jbase + b;
            r++;
        }
    }
    if (lane == 0) g_rcount[i] = min(total, ROWCAP);
}

__global__ void __launch_bounds__(256) k_rscan() {
    const int PER = 32;  // 256 * 32 = 8192 >= NA
    __shared__ int wsum[8];
    int t = threadIdx.x;
    int v[PER];
    int s = 0;
    #pragma unroll
    for (int u = 0; u < PER; u++) {
        int idx = t * PER + u;
        v[u] = (idx < NA) ? g_rcount[idx] : 0;
        s += v[u];
    }
    int ln = t & 31, wd = t >> 5;
    int x = s;
    #pragma unroll
    for (int d = 1; d < 32; d <<= 1) {
        int y = __shfl_up_sync(0xFFFFFFFFu, x, d);
        if (ln >= d) x += y;
    }
    if (ln == 31) wsum[wd] = x;
    __syncthreads();
    if (t == 0) {
        int acc = 0;
        #pragma unroll
        for (int w = 0; w < 8; w++) { int tmp = wsum[w]; wsum[w] = acc; acc += tmp; }
        g_total = acc;
    }
    __syncthreads();
    int excl = wsum[wd] + (x - s);
    #pragma unroll
    for (int u = 0; u < PER; u++) {
        int idx = t * PER + u;
        if (idx < NA) g_roff[idx] = excl;
        excl += v[u];
    }
}

__global__ void __launch_bounds__(RPB * 32) k_emit(float* __restrict__ out) {
    int warp = threadIdx.x >> 5;
    int lane = threadIdx.x & 31;
    int i = blockIdx.x * RPB + warp;
    {
        int c = g_rcount[i];
        int o = g_roff[i];
        float4 pi = g_pos4[i];
        float fi = (float)i;
        for (int k = lane; k < c; k += 32) {
            int idx = o + k;
            if (idx < MP) {
                int j = g_scratch[i * ROWCAP + k];
                float4 pj = g_pos4[j];
                float dx = pj.x - pi.x;
                float dy = pj.y - pi.y;
                float dz = pj.z - pi.z;
                float ds = sqrtf(dx * dx + dy * dy + dz * dz);
                ((float2*)out)[idx] = make_float2(fi, (float)j);
                out[2 * MP + idx] = (i < j) ? 1.0f : 0.0f;
                out[3 * MP + idx] = ds;
            }
        }
    }
    // zero-fill only the padding tail [total, MP) of each section
    int total = g_total;
    int tid = blockIdx.x * blockDim.x + threadIdx.x;
    int stride = gridDim.x * blockDim.x;
    for (int idx = total + tid; idx < MP; idx += stride) {
        ((float2*)out)[idx] = make_float2(0.f, 0.f);
        out[2 * MP + idx] = 0.f;
        out[3 * MP + idx] = 0.f;
    }
}

// ---------------- launch ----------------
extern "C" void kernel_launch(void* const* d_in, const int* in_sizes, int n_in,
                              void* d_out, int out_size) {
    const float* pos = (const float*)d_in[0];
    float* out = (float*)d_out;

    k_prep<<<(NA + 255) / 256, 256>>>(pos);
    k_build<<<1, 1024>>>();
    k_rows<<<NA / RPB, RPB * 32>>>();
    k_rscan<<<1, 256>>>();
    k_emit<<<NA / RPB, RPB * 32>>>(out);
}

// round 7
// speedup vs baseline: 1.2745x; 1.0879x over previous
#include <cuda_runtime.h>

#define NA      8000
#define MP      1200000
#define NCDIM   8
#define NCELL   512
#define ROWCAP  192
#define RPB     16     /* rows (warps) per block in k_rows / k_emit */

// ---------------- device scratch (no allocations allowed) ----------------
__device__ float4 g_pos4[NA];        // original order: x,y,z,|p|^2
__device__ float4 g_pos4s[NA];       // cell-sorted: x,y,z,bitcast(orig index)
__device__ int    g_cstart[NCELL + 1];
__device__ int    g_rcount[8192];    // [NA..8192) stays zero forever (never written)
__device__ int    g_roff[NA];
__device__ int    g_total;
__device__ int    g_scratch[NA * ROWCAP];

__device__ __forceinline__ int cellco(float x) {
    int c = (int)(x * 0.2f);
    return min(7, max(0, c));
}

// ---------------- fused prep + cell build (one block, smem counters) ------
__global__ void __launch_bounds__(1024) k_build(const float* __restrict__ pos) {
    __shared__ int sh[NCELL];
    __shared__ int cur[NCELL];
    int t = threadIdx.x;
    if (t < NCELL) sh[t] = 0;
    __syncthreads();

    float4 loc[8];
    int    cid[8];
    #pragma unroll
    for (int u = 0; u < 8; u++) {
        int i = t + u * 1024;
        cid[u] = -1;
        if (i < NA) {
            float x = pos[3 * i + 0];
            float y = pos[3 * i + 1];
            float z = pos[3 * i + 2];
            // sq = (x*x + y*y) + z*z, strict fp32, NO FMA (XLA mul+reduce fusion)
            float sq = __fadd_rn(__fadd_rn(__fmul_rn(x, x), __fmul_rn(y, y)),
                                 __fmul_rn(z, z));
            loc[u] = make_float4(x, y, z, sq);
            g_pos4[i] = loc[u];
            int c = (cellco(z) * NCDIM + cellco(y)) * NCDIM + cellco(x);
            cid[u] = c;
            atomicAdd(&sh[c], 1);
        }
    }
    __syncthreads();

    // Hillis-Steele inclusive scan over 512 cells (first 512 threads)
    int v0 = (t < NCELL) ? sh[t] : 0;
    for (int d = 1; d < NCELL; d <<= 1) {
        int v = 0;
        if (t < NCELL && t >= d) v = sh[t - d];
        __syncthreads();
        if (t < NCELL) sh[t] += v;
        __syncthreads();
    }
    if (t < NCELL) {
        int incl = sh[t];
        int excl = incl - v0;
        g_cstart[t] = excl;
        cur[t] = excl;
        if (t == NCELL - 1) g_cstart[NCELL] = incl;
    }
    __syncthreads();

    #pragma unroll
    for (int u = 0; u < 8; u++) {
        if (cid[u] >= 0) {
            int i = t + u * 1024;
            int p = atomicAdd(&cur[cid[u]], 1);
            g_pos4s[p] = make_float4(loc[u].x, loc[u].y, loc[u].z, __int_as_float(i));
        }
    }
}

__global__ void __launch_bounds__(RPB * 32) k_rows() {
    __shared__ unsigned mask[RPB][256];
    int warp = threadIdx.x >> 5;
    int lane = threadIdx.x & 31;
    int i = blockIdx.x * RPB + warp;
    unsigned* m = mask[warp];
    #pragma unroll
    for (int w = lane; w < 256; w += 32) m[w] = 0u;
    __syncwarp();

    float4 pi = g_pos4[i];
    int cx = cellco(pi.x), cy = cellco(pi.y), cz = cellco(pi.z);
    // dist < 5  <=>  RN(sqrt(d2)) < 5  <=>  d2 < nextbelow(25.0f)
    const float T = __int_as_float(0x41C7FFFF);
    int zlo = max(cz - 1, 0), zhi = min(cz + 1, 7);
    int ylo = max(cy - 1, 0), yhi = min(cy + 1, 7);
    int xlo = max(cx - 1, 0), xhi = min(cx + 1, 7);
    for (int zz = zlo; zz <= zhi; zz++)
        for (int yy = ylo; yy <= yhi; yy++) {
            int crow = (zz * NCDIM + yy) * NCDIM;
            int s = g_cstart[crow + xlo];
            int e = g_cstart[crow + xhi + 1];   // x-adjacent cells are contiguous
            for (int k = s + lane; k < e; k += 32) {
                float4 pj = g_pos4s[k];
                // sq_j recomputed with the exact k_prep sequence (bit-identical)
                float sqj = __fadd_rn(__fadd_rn(__fmul_rn(pj.x, pj.x),
                                                __fmul_rn(pj.y, pj.y)),
                                      __fmul_rn(pj.z, pj.z));
                // Eigen-style FMA chain: dot = fma(z, fma(y, rn(x*x')))
                float dt = __fmaf_rn(pi.z, pj.z,
                            __fmaf_rn(pi.y, pj.y,
                             __fmul_rn(pi.x, pj.x)));
                float d2 = __fsub_rn(__fadd_rn(pi.w, sqj), __fmul_rn(2.0f, dt));
                int j = __float_as_int(pj.w);
                if (d2 < T && j != i)
                    atomicOr(&m[j >> 5], 1u << (j & 31));
            }
        }
    __syncwarp();

    // lane-parallel ordered (ascending-j) emission: lane owns words [8l, 8l+8)
    unsigned words[8];
    int cnt = 0;
    uint4 wa = ((const uint4*)m)[lane * 2 + 0];
    uint4 wb = ((const uint4*)m)[lane * 2 + 1];
    words[0] = wa.x; words[1] = wa.y; words[2] = wa.z; words[3] = wa.w;
    words[4] = wb.x; words[5] = wb.y; words[6] = wb.z; words[7] = wb.w;
    #pragma unroll
    for (int u = 0; u < 8; u++) cnt += __popc(words[u]);
    int x = cnt;
    #pragma unroll
    for (int d = 1; d < 32; d <<= 1) {
        int y = __shfl_up_sync(0xFFFFFFFFu, x, d);
        if (lane >= d) x += y;
    }
    int r = x - cnt;                                   // exclusive prefix
    int total = __shfl_sync(0xFFFFFFFFu, x, 31);
    int base = i * ROWCAP;
    #pragma unroll
    for (int u = 0; u < 8; u++) {
        unsigned mm = words[u];
        int jbase = (lane * 8 + u) * 32;
        while (mm) {
            int b = __ffs(mm) - 1;
            mm &= mm - 1;
            if (r < ROWCAP) g_scratch[base + r] = jbase + b;
            r++;
        }
    }
    if (lane == 0) g_rcount[i] = min(total, ROWCAP);
}

// single-block scan, coalesced int4 loads staged through smem
__global__ void __launch_bounds__(256) k_rscan() {
    __shared__ int s_cnt[8192];
    __shared__ int wsum[8];
    int t = threadIdx.x;
    #pragma unroll
    for (int r = 0; r < 8; r++) {
        ((int4*)s_cnt)[r * 256 + t] = ((const int4*)g_rcount)[r * 256 + t];
    }
    __syncthreads();

    const int PER = 32;
    int v[PER];
    int s = 0;
    #pragma unroll
    for (int u = 0; u < PER; u++) {
        v[u] = s_cnt[t * PER + u];
        s += v[u];
    }
    int ln = t & 31, wd = t >> 5;
    int x = s;
    #pragma unroll
    for (int d = 1; d < 32; d <<= 1) {
        int y = __shfl_up_sync(0xFFFFFFFFu, x, d);
        if (ln >= d) x += y;
    }
    if (ln == 31) wsum[wd] = x;
    __syncthreads();
    if (t == 0) {
        int acc = 0;
        #pragma unroll
        for (int w = 0; w < 8; w++) { int tmp = wsum[w]; wsum[w] = acc; acc += tmp; }
        g_total = acc;
    }
    __syncthreads();
    int excl = wsum[wd] + (x - s);
    #pragma unroll
    for (int u = 0; u < PER; u++) {
        int idx = t * PER + u;
        if (idx < NA) g_roff[idx] = excl;
        excl += v[u];
    }
}

__global__ void __launch_bounds__(RPB * 32) k_emit(float* __restrict__ out) {
    int warp = threadIdx.x >> 5;
    int lane = threadIdx.x & 31;
    int i = blockIdx.x * RPB + warp;
    {
        int c = g_rcount[i];
        int o = g_roff[i];
        float4 pi = g_pos4[i];
        float fi = (float)i;
        for (int k = lane; k < c; k += 32) {
            int idx = o + k;
            if (idx < MP) {
                int j = g_scratch[i * ROWCAP + k];
                float4 pj = g_pos4[j];
                float dx = pj.x - pi.x;
                float dy = pj.y - pi.y;
                float dz = pj.z - pi.z;
                float ds = sqrtf(dx * dx + dy * dy + dz * dz);
                ((float2*)out)[idx] = make_float2(fi, (float)j);
                out[2 * MP + idx] = (i < j) ? 1.0f : 0.0f;
                out[3 * MP + idx] = ds;
            }
        }
    }
    // zero-fill only the padding tail [total, MP) of each section
    int total = g_total;
    int tid = blockIdx.x * blockDim.x + threadIdx.x;
    int stride = gridDim.x * blockDim.x;
    for (int idx = total + tid; idx < MP; idx += stride) {
        ((float2*)out)[idx] = make_float2(0.f, 0.f);
        out[2 * MP + idx] = 0.f;
        out[3 * MP + idx] = 0.f;
    }
}

// ---------------- launch ----------------
extern "C" void kernel_launch(void* const* d_in, const int* in_sizes, int n_in,
                              void* d_out, int out_size) {
    const float* pos = (const float*)d_in[0];
    float* out = (float*)d_out;

    k_build<<<1, 1024>>>(pos);
    k_rows<<<NA / RPB, RPB * 32>>>();
    k_rscan<<<1, 256>>>();
    k_emit<<<NA / RPB, RPB * 32>>>(out);
}

// round 9
// speedup vs baseline: 1.3542x; 1.0626x over previous
#include <cuda_runtime.h>

#define NA      8000
#define MP      1200000
#define NCDIM   8
#define NCELL   512
#define ROWCAP  192
#define RPB     16     /* rows (warps) per block in k_rows */
#define EPB     8      /* rows per block in k_emit (2 warps per row) */
#define NBLK    (NA / RPB)

// ---------------- device scratch (no allocations allowed) ----------------
__device__ float4 g_pos4[NA];        // original order: x,y,z,|p|^2
__device__ float4 g_pos4s[NA];       // cell-sorted: x,y,z,bitcast(orig index)
__device__ int    g_cstart[NCELL + 1];
__device__ int    g_rcount[8192];    // [NA..8192) stays zero forever (never written)
__device__ int    g_roff[8192];
__device__ int    g_total;
__device__ int    g_done;            // self-restoring ticket
__device__ int    g_scratch[NA * ROWCAP];

__device__ __forceinline__ int cellco(float x) {
    int c = (int)(x * 0.2f);
    return min(7, max(0, c));
}

// ---------------- fused prep + cell build (one block, smem counters) ------
__global__ void __launch_bounds__(1024) k_build(const float* __restrict__ pos) {
    __shared__ int sh[NCELL];
    __shared__ int cur[NCELL];
    int t = threadIdx.x;
    if (t < NCELL) sh[t] = 0;
    __syncthreads();

    float4 loc[8];
    int    cid[8];
    #pragma unroll
    for (int u = 0; u < 8; u++) {
        int i = t + u * 1024;
        cid[u] = -1;
        if (i < NA) {
            float x = pos[3 * i + 0];
            float y = pos[3 * i + 1];
            float z = pos[3 * i + 2];
            // sq = (x*x + y*y) + z*z, strict fp32, NO FMA (XLA mul+reduce fusion)
            float sq = __fadd_rn(__fadd_rn(__fmul_rn(x, x), __fmul_rn(y, y)),
                                 __fmul_rn(z, z));
            loc[u] = make_float4(x, y, z, sq);
            g_pos4[i] = loc[u];
            int c = (cellco(z) * NCDIM + cellco(y)) * NCDIM + cellco(x);
            cid[u] = c;
            atomicAdd(&sh[c], 1);
        }
    }
    __syncthreads();

    // Hillis-Steele inclusive scan over 512 cells (first 512 threads)
    int v0 = (t < NCELL) ? sh[t] : 0;
    for (int d = 1; d < NCELL; d <<= 1) {
        int v = 0;
        if (t < NCELL && t >= d) v = sh[t - d];
        __syncthreads();
        if (t < NCELL) sh[t] += v;
        __syncthreads();
    }
    if (t < NCELL) {
        int incl = sh[t];
        int excl = incl - v0;
        g_cstart[t] = excl;
        cur[t] = excl;
        if (t == NCELL - 1) g_cstart[NCELL] = incl;
    }
    __syncthreads();

    #pragma unroll
    for (int u = 0; u < 8; u++) {
        if (cid[u] >= 0) {
            int i = t + u * 1024;
            int p = atomicAdd(&cur[cid[u]], 1);
            g_pos4s[p] = make_float4(loc[u].x, loc[u].y, loc[u].z, __int_as_float(i));
        }
    }
}

__global__ void __launch_bounds__(RPB * 32, 4) k_rows() {
    __shared__ unsigned mask[RPB][256];
    __shared__ int wsum[16];
    __shared__ int s_last;
    int warp = threadIdx.x >> 5;
    int lane = threadIdx.x & 31;
    int i = blockIdx.x * RPB + warp;
    unsigned* m = mask[warp];
    #pragma unroll
    for (int w = lane; w < 256; w += 32) m[w] = 0u;
    __syncwarp();

    float4 pi = g_pos4[i];
    int cx = cellco(pi.x), cy = cellco(pi.y), cz = cellco(pi.z);
    // dist < 5  <=>  RN(sqrt(d2)) < 5  <=>  d2 < nextbelow(25.0f)
    const float T = __int_as_float(0x41C7FFFF);
    int zlo = max(cz - 1, 0), zhi = min(cz + 1, 7);
    int ylo = max(cy - 1, 0), yhi = min(cy + 1, 7);
    int xlo = max(cx - 1, 0), xhi = min(cx + 1, 7);
    for (int zz = zlo; zz <= zhi; zz++)
        for (int yy = ylo; yy <= yhi; yy++) {
            int crow = (zz * NCDIM + yy) * NCDIM;
            int s = g_cstart[crow + xlo];
            int e = g_cstart[crow + xhi + 1];   // x-adjacent cells are contiguous
            for (int k = s + lane; k < e; k += 32) {
                float4 pj = g_pos4s[k];
                // sq_j recomputed with the exact k_build sequence (bit-identical)
                float sqj = __fadd_rn(__fadd_rn(__fmul_rn(pj.x, pj.x),
                                                __fmul_rn(pj.y, pj.y)),
                                      __fmul_rn(pj.z, pj.z));
                // Eigen-style FMA chain: dot = fma(z, fma(y, rn(x*x')))
                float dt = __fmaf_rn(pi.z, pj.z,
                            __fmaf_rn(pi.y, pj.y,
                             __fmul_rn(pi.x, pj.x)));
                float d2 = __fsub_rn(__fadd_rn(pi.w, sqj), __fmul_rn(2.0f, dt));
                int j = __float_as_int(pj.w);
                if (d2 < T && j != i)
                    atomicOr(&m[j >> 5], 1u << (j & 31));
            }
        }
    __syncwarp();

    // lane-parallel ordered (ascending-j) emission: lane owns words [8l, 8l+8)
    unsigned words[8];
    int cnt = 0;
    uint4 wa = ((const uint4*)m)[lane * 2 + 0];
    uint4 wb = ((const uint4*)m)[lane * 2 + 1];
    words[0] = wa.x; words[1] = wa.y; words[2] = wa.z; words[3] = wa.w;
    words[4] = wb.x; words[5] = wb.y; words[6] = wb.z; words[7] = wb.w;
    #pragma unroll
    for (int u = 0; u < 8; u++) cnt += __popc(words[u]);
    int x = cnt;
    #pragma unroll
    for (int d = 1; d < 32; d <<= 1) {
        int y = __shfl_up_sync(0xFFFFFFFFu, x, d);
        if (lane >= d) x += y;
    }
    int r = x - cnt;                                   // exclusive prefix
    int total = __shfl_sync(0xFFFFFFFFu, x, 31);
    int base = i * ROWCAP;
    #pragma unroll
    for (int u = 0; u < 8; u++) {
        unsigned mm = words[u];
        int jbase = (lane * 8 + u) * 32;
        while (mm) {
            int b = __ffs(mm) - 1;
            mm &= mm - 1;
            if (r < ROWCAP) g_scratch[base + r] = jbase + b;
            r++;
        }
    }
    if (lane == 0) {
        g_rcount[i] = min(total, ROWCAP);
        __threadfence();                 // release: rcount visible before ticket
    }
    __syncthreads();
    if (threadIdx.x == 0) s_last = atomicAdd(&g_done, 1);
    __syncthreads();
    if (s_last != NBLK - 1) return;

    // ---- last block: row-offset scan over 8192 counts ----
    if (threadIdx.x == 0) g_done = 0;    // restore invariant for next replay
    __threadfence();                     // acquire side
    {
        int t = threadIdx.x;
        // L1-bypass loads (other SMs' writes; avoid stale-line hazard)
        int4 a0 = __ldcg((const int4*)g_rcount + t * 4 + 0);
        int4 a1 = __ldcg((const int4*)g_rcount + t * 4 + 1);
        int4 a2 = __ldcg((const int4*)g_rcount + t * 4 + 2);
        int4 a3 = __ldcg((const int4*)g_rcount + t * 4 + 3);
        int s = a0.x + a0.y + a0.z + a0.w + a1.x + a1.y + a1.z + a1.w
              + a2.x + a2.y + a2.z + a2.w + a3.x + a3.y + a3.z + a3.w;
        int xx = s;
        #pragma unroll
        for (int d = 1; d < 32; d <<= 1) {
            int y = __shfl_up_sync(0xFFFFFFFFu, xx, d);
            if (lane >= d) xx += y;
        }
        if (lane == 31) wsum[warp] = xx;
        __syncthreads();
        if (warp == 0) {
            int z = (lane < 16) ? wsum[lane] : 0;
            int x2 = z;
            #pragma unroll
            for (int d = 1; d < 32; d <<= 1) {
                int y = __shfl_up_sync(0xFFFFFFFFu, x2, d);
                if (lane >= d) x2 += y;
            }
            if (lane < 16) wsum[lane] = x2 - z;   // exclusive warp base
            if (lane == 15) g_total = x2;
        }
        __syncthreads();
        int run = wsum[warp] + (xx - s);
        int4 o;
        o.x = run; run += a0.x; o.y = run; run += a0.y;
        o.z = run; run += a0.z; o.w = run; run += a0.w;
        ((int4*)g_roff)[t * 4 + 0] = o;
        o.x = run; run += a1.x; o.y = run; run += a1.y;
        o.z = run; run += a1.z; o.w = run; run += a1.w;
        ((int4*)g_roff)[t * 4 + 1] = o;
        o.x = run; run += a2.x; o.y = run; run += a2.y;
        o.z = run; run += a2.z; o.w = run; run += a2.w;
        ((int4*)g_roff)[t * 4 + 2] = o;
        o.x = run; run += a3.x; o.y = run; run += a3.y;
        o.z = run; run += a3.z; o.w = run; run += a3.w;
        ((int4*)g_roff)[t * 4 + 3] = o;
    }
}

__global__ void __launch_bounds__(512) k_emit(float* __restrict__ out) {
    int w = threadIdx.x >> 5;
    int lane = threadIdx.x & 31;
    int i = blockIdx.x * EPB + (w >> 1);          // 2 warps per row
    int lanein = ((w & 1) << 5) + lane;           // 0..63 within the row
    {
        int c = g_rcount[i];
        int o = g_roff[i];
        float4 pi = g_pos4[i];
        float fi = (float)i;
        for (int k = lanein; k < c; k += 64) {
            int idx = o + k;
            if (idx < MP) {
                int j = g_scratch[i * ROWCAP + k];
                float4 pj = g_pos4[j];
                float dx = pj.x - pi.x;
                float dy = pj.y - pi.y;
                float dz = pj.z - pi.z;
                float ds = sqrtf(dx * dx + dy * dy + dz * dz);
                ((float2*)out)[idx] = make_float2(fi, (float)j);
                out[2 * MP + idx] = (i < j) ? 1.0f : 0.0f;
                out[3 * MP + idx] = ds;
            }
        }
    }
    // zero-fill only the padding tail [total, MP) of each section
    int total = g_total;
    int tid = blockIdx.x * blockDim.x + threadIdx.x;
    int stride = gridDim.x * blockDim.x;
    for (int idx = total + tid; idx < MP; idx += stride) {
        ((float2*)out)[idx] = make_float2(0.f, 0.f);
        out[2 * MP + idx] = 0.f;
        out[3 * MP + idx] = 0.f;
    }
}

// ---------------- launch ----------------
extern "C" void kernel_launch(void* const* d_in, const int* in_sizes, int n_in,
                              void* d_out, int out_size) {
    const float* pos = (const float*)d_in[0];
    float* out = (float*)d_out;

    k_build<<<1, 1024>>>(pos);
    k_rows<<<NBLK, RPB * 32>>>();
    k_emit<<<NA / EPB, 512>>>(out);
}

// round 11
// speedup vs baseline: 1.4272x; 1.0539x over previous
#include <cuda_runtime.h>

#define NA      8000
#define MP      1200000
#define NCDIM   8
#define NCELL   512
#define ROWCAP  192
#define RPB     16     /* rows (warps) per block in k_rows */
#define EPB     8      /* rows per block in k_emit (2 warps per row) */
#define NBLK    (NA / RPB)
#define CBLK    32     /* blocks in k_count / k_scatter */

// ---------------- device scratch (no allocations allowed) ----------------
__device__ float4 g_pos4[NA];        // original order: x,y,z,|p|^2
__device__ float4 g_pos4s[NA];       // cell-sorted: x,y,z,bitcast(orig index)
__device__ int    g_ccount[NCELL];   // zero at start of every call (self-restoring)
__device__ int    g_cstart[NCELL + 1];
__device__ int    g_ccursor[NCELL];
__device__ int    g_rcount[8192];    // [NA..8192) stays zero forever (never written)
__device__ int    g_roff[8192];
__device__ int    g_total;
__device__ int    g_done_c;          // self-restoring ticket (count)
__device__ int    g_done_r;          // self-restoring ticket (rows)
__device__ int    g_scratch[NA * ROWCAP];

__device__ __forceinline__ int cellco(float x) {
    int c = (int)(x * 0.2f);
    return min(7, max(0, c));
}

// ---------- pass 1: per-atom prep + global cell histogram + ticket scan ----
__global__ void __launch_bounds__(256) k_count(const float* __restrict__ pos) {
    int i = blockIdx.x * 256 + threadIdx.x;
    if (i < NA) {
        float x = pos[3 * i + 0];
        float y = pos[3 * i + 1];
        float z = pos[3 * i + 2];
        // sq = (x*x + y*y) + z*z, strict fp32, NO FMA (XLA mul+reduce fusion)
        float sq = __fadd_rn(__fadd_rn(__fmul_rn(x, x), __fmul_rn(y, y)),
                             __fmul_rn(z, z));
        g_pos4[i] = make_float4(x, y, z, sq);
        int c = (cellco(z) * NCDIM + cellco(y)) * NCDIM + cellco(x);
        atomicAdd(&g_ccount[c], 1);
    }
    // ---- ticket: last block scans the 512 cell counts ----
    __shared__ int s_last;
    __shared__ int wsum[8];
    __threadfence();
    __syncthreads();
    if (threadIdx.x == 0) s_last = atomicAdd(&g_done_c, 1);
    __syncthreads();
    if (s_last != CBLK - 1) return;
    if (threadIdx.x == 0) g_done_c = 0;   // restore invariant
    __threadfence();

    int t = threadIdx.x;
    int lane = t & 31, wd = t >> 5;
    // each thread owns cells 2t, 2t+1 (atomics live in L2; __ldcg avoids L1)
    int c0 = __ldcg(&g_ccount[2 * t + 0]);
    int c1 = __ldcg(&g_ccount[2 * t + 1]);
    int s = c0 + c1;
    int x = s;
    #pragma unroll
    for (int d = 1; d < 32; d <<= 1) {
        int y = __shfl_up_sync(0xFFFFFFFFu, x, d);
        if (lane >= d) x += y;
    }
    if (lane == 31) wsum[wd] = x;
    __syncthreads();
    if (wd == 0) {
        int z = (lane < 8) ? wsum[lane] : 0;
        int x2 = z;
        #pragma unroll
        for (int d = 1; d < 8; d <<= 1) {
            int y = __shfl_up_sync(0xFFFFFFFFu, x2, d);
            if (lane >= d) x2 += y;
        }
        if (lane < 8) wsum[lane] = x2 - z;  // exclusive warp base
    }
    __syncthreads();
    int excl = wsum[wd] + (x - s);
    g_cstart[2 * t + 0] = excl;
    g_ccursor[2 * t + 0] = excl;
    g_cstart[2 * t + 1] = excl + c0;
    g_ccursor[2 * t + 1] = excl + c0;
    g_ccount[2 * t + 0] = 0;              // restore invariant
    g_ccount[2 * t + 1] = 0;
    if (t == 255) g_cstart[NCELL] = excl + c0 + c1;
}

// ---------- pass 2: parallel scatter into cell-sorted order ----------
__global__ void __launch_bounds__(256) k_scatter() {
    int i = blockIdx.x * 256 + threadIdx.x;
    if (i >= NA) return;
    float4 q = g_pos4[i];
    int c = (cellco(q.z) * NCDIM + cellco(q.y)) * NCDIM + cellco(q.x);
    int p = atomicAdd(&g_ccursor[c], 1);
    g_pos4s[p] = make_float4(q.x, q.y, q.z, __int_as_float(i));
}

__global__ void __launch_bounds__(RPB * 32, 4) k_rows() {
    __shared__ unsigned mask[RPB][256];
    __shared__ int wsum[16];
    __shared__ int s_last;
    int warp = threadIdx.x >> 5;
    int lane = threadIdx.x & 31;
    int i = blockIdx.x * RPB + warp;
    unsigned* m = mask[warp];
    #pragma unroll
    for (int w = lane; w < 256; w += 32) m[w] = 0u;
    __syncwarp();

    float4 pi = g_pos4[i];
    int cx = cellco(pi.x), cy = cellco(pi.y), cz = cellco(pi.z);
    // dist < 5  <=>  RN(sqrt(d2)) < 5  <=>  d2 < nextbelow(25.0f)
    const float T = __int_as_float(0x41C7FFFF);
    int zlo = max(cz - 1, 0), zhi = min(cz + 1, 7);
    int ylo = max(cy - 1, 0), yhi = min(cy + 1, 7);
    int xlo = max(cx - 1, 0), xhi = min(cx + 1, 7);
    for (int zz = zlo; zz <= zhi; zz++)
        for (int yy = ylo; yy <= yhi; yy++) {
            int crow = (zz * NCDIM + yy) * NCDIM;
            int s = g_cstart[crow + xlo];
            int e = g_cstart[crow + xhi + 1];   // x-adjacent cells are contiguous
            for (int k = s + lane; k < e; k += 32) {
                float4 pj = g_pos4s[k];
                // sq_j recomputed with the exact k_count sequence (bit-identical)
                float sqj = __fadd_rn(__fadd_rn(__fmul_rn(pj.x, pj.x),
                                                __fmul_rn(pj.y, pj.y)),
                                      __fmul_rn(pj.z, pj.z));
                // Eigen-style FMA chain: dot = fma(z, fma(y, rn(x*x')))
                float dt = __fmaf_rn(pi.z, pj.z,
                            __fmaf_rn(pi.y, pj.y,
                             __fmul_rn(pi.x, pj.x)));
                float d2 = __fsub_rn(__fadd_rn(pi.w, sqj), __fmul_rn(2.0f, dt));
                int j = __float_as_int(pj.w);
                if (d2 < T && j != i)
                    atomicOr(&m[j >> 5], 1u << (j & 31));
            }
        }
    __syncwarp();

    // lane-parallel ordered (ascending-j) emission: lane owns words [8l, 8l+8)
    unsigned words[8];
    int cnt = 0;
    uint4 wa = ((const uint4*)m)[lane * 2 + 0];
    uint4 wb = ((const uint4*)m)[lane * 2 + 1];
    words[0] = wa.x; words[1] = wa.y; words[2] = wa.z; words[3] = wa.w;
    words[4] = wb.x; words[5] = wb.y; words[6] = wb.z; words[7] = wb.w;
    #pragma unroll
    for (int u = 0; u < 8; u++) cnt += __popc(words[u]);
    int x = cnt;
    #pragma unroll
    for (int d = 1; d < 32; d <<= 1) {
        int y = __shfl_up_sync(0xFFFFFFFFu, x, d);
        if (lane >= d) x += y;
    }
    int r = x - cnt;                                   // exclusive prefix
    int total = __shfl_sync(0xFFFFFFFFu, x, 31);
    int base = i * ROWCAP;
    #pragma unroll
    for (int u = 0; u < 8; u++) {
        unsigned mm = words[u];
        int jbase = (lane * 8 + u) * 32;
        while (mm) {
            int b = __ffs(mm) - 1;
            mm &= mm - 1;
            if (r < ROWCAP) g_scratch[base + r] = jbase + b;
            r++;
        }
    }
    if (lane == 0) {
        g_rcount[i] = min(total, ROWCAP);
        __threadfence();                 // release: rcount visible before ticket
    }
    __syncthreads();
    if (threadIdx.x == 0) s_last = atomicAdd(&g_done_r, 1);
    __syncthreads();
    if (s_last != NBLK - 1) return;

    // ---- last block: row-offset scan over 8192 counts ----
    if (threadIdx.x == 0) g_done_r = 0;  // restore invariant for next replay
    __threadfence();                     // acquire side
    {
        int t = threadIdx.x;
        // L1-bypass loads (other SMs' writes; avoid stale-line hazard)
        int4 a0 = __ldcg((const int4*)g_rcount + t * 4 + 0);
        int4 a1 = __ldcg((const int4*)g_rcount + t * 4 + 1);
        int4 a2 = __ldcg((const int4*)g_rcount + t * 4 + 2);
        int4 a3 = __ldcg((const int4*)g_rcount + t * 4 + 3);
        int s = a0.x + a0.y + a0.z + a0.w + a1.x + a1.y + a1.z + a1.w
              + a2.x + a2.y + a2.z + a2.w + a3.x + a3.y + a3.z + a3.w;
        int xx = s;
        #pragma unroll
        for (int d = 1; d < 32; d <<= 1) {
            int y = __shfl_up_sync(0xFFFFFFFFu, xx, d);
            if (lane >= d) xx += y;
        }
        if (lane == 31) wsum[warp] = xx;
        __syncthreads();
        if (warp == 0) {
            int z = (lane < 16) ? wsum[lane] : 0;
            int x2 = z;
            #pragma unroll
            for (int d = 1; d < 32; d <<= 1) {
                int y = __shfl_up_sync(0xFFFFFFFFu, x2, d);
                if (lane >= d) x2 += y;
            }
            if (lane < 16) wsum[lane] = x2 - z;   // exclusive warp base
            if (lane == 15) g_total = x2;
        }
        __syncthreads();
        int run = wsum[warp] + (xx - s);
        int4 o;
        o.x = run; run += a0.x; o.y = run; run += a0.y;
        o.z = run; run += a0.z; o.w = run; run += a0.w;
        ((int4*)g_roff)[t * 4 + 0] = o;
        o.x = run; run += a1.x; o.y = run; run += a1.y;
        o.z = run; run += a1.z; o.w = run; run += a1.w;
        ((int4*)g_roff)[t * 4 + 1] = o;
        o.x = run; run += a2.x; o.y = run; run += a2.y;
        o.z = run; run += a2.z; o.w = run; run += a2.w;
        ((int4*)g_roff)[t * 4 + 2] = o;
        o.x = run; run += a3.x; o.y = run; run += a3.y;
        o.z = run; run += a3.z; o.w = run; run += a3.w;
        ((int4*)g_roff)[t * 4 + 3] = o;
    }
}

__global__ void __launch_bounds__(512) k_emit(float* __restrict__ out) {
    int w = threadIdx.x >> 5;
    int lane = threadIdx.x & 31;
    int i = blockIdx.x * EPB + (w >> 1);          // 2 warps per row
    int lanein = ((w & 1) << 5) + lane;           // 0..63 within the row
    {
        int c = g_rcount[i];
        int o = g_roff[i];
        float4 pi = g_pos4[i];
        float fi = (float)i;
        for (int k = lanein; k < c; k += 64) {
            int idx = o + k;
            if (idx < MP) {
                int j = g_scratch[i * ROWCAP + k];
                float4 pj = g_pos4[j];
                float dx = pj.x - pi.x;
                float dy = pj.y - pi.y;
                float dz = pj.z - pi.z;
                float ds = sqrtf(dx * dx + dy * dy + dz * dz);
                ((float2*)out)[idx] = make_float2(fi, (float)j);
                out[2 * MP + idx] = (i < j) ? 1.0f : 0.0f;
                out[3 * MP + idx] = ds;
            }
        }
    }
    // zero-fill only the padding tail [total, MP) of each section
    int total = g_total;
    int tid = blockIdx.x * blockDim.x + threadIdx.x;
    int stride = gridDim.x * blockDim.x;
    for (int idx = total + tid; idx < MP; idx += stride) {
        ((float2*)out)[idx] = make_float2(0.f, 0.f);
        out[2 * MP + idx] = 0.f;
        out[3 * MP + idx] = 0.f;
    }
}

// ---------------- launch ----------------
extern "C" void kernel_launch(void* const* d_in, const int* in_sizes, int n_in,
                              void* d_out, int out_size) {
    const float* pos = (const float*)d_in[0];
    float* out = (float*)d_out;

    k_count<<<CBLK, 256>>>(pos);
    k_scatter<<<CBLK, 256>>>();
    k_rows<<<NBLK, RPB * 32>>>();
    k_emit<<<NA / EPB, 512>>>(out);
}